// round 13
// baseline (speedup 1.0000x reference)
#include <cuda_runtime.h>
#include <cstdint>

// EdgeFeature: B=4, D=64, N=4096, K=16
// out = [ edge_feature (4,128,4096,16) fp32 ; idx (4,65536) as fp32 ]

#define B_ 4
#define D_ 64
#define N_ 4096
#define K_ 16

// Scratch (static __device__ — no allocations allowed in kernel_launch)
__device__ float g_sq[B_ * N_];                       // 64 KB
__device__ float g_dist[(size_t)B_ * N_ * N_];        // 256 MB
__device__ int   g_idx[B_ * N_ * K_];                 // 1 MB

// packed f32x2 FMA: both lanes are independent IEEE fp32 FMAs -> bitwise
// identical to scalar fmaf chains (validated rel_err==0 across rounds).
__device__ __forceinline__ void fma2(unsigned long long& c,
                                     unsigned long long a, unsigned long long b) {
    asm("fma.rn.f32x2 %0, %1, %2, %0;" : "+l"(c) : "l"(a), "l"(b));
}

__device__ __forceinline__ uint32_t smem_u32(const void* p) {
    uint32_t a;
    asm("{ .reg .u64 t; cvta.to.shared.u64 t, %1; cvt.u32.u64 %0, t; }"
        : "=r"(a) : "l"(p));
    return a;
}
__device__ __forceinline__ void cpasync16(uint32_t saddr, const void* g) {
    asm volatile("cp.async.ca.shared.global [%0], [%1], 16;"
                 :: "r"(saddr), "l"(g) : "memory");
}
__device__ __forceinline__ void cpcommit() {
    asm volatile("cp.async.commit_group;" ::: "memory");
}
template <int N>
__device__ __forceinline__ void cpwait() {
    asm volatile("cp.async.wait_group %0;" :: "n"(N) : "memory");
}

// ---------------------------------------------------------------------------
// 1) squared norms (sequential ascending d, fmaf — matches the GEMM's dot
//    accumulation order so self-distance cancels to exactly 0.0f)
// ---------------------------------------------------------------------------
__global__ void sq_kernel(const float* __restrict__ pc) {
    int gid = blockIdx.x * blockDim.x + threadIdx.x;
    int b = gid >> 12;
    int n = gid & (N_ - 1);
    const float* X = pc + (size_t)b * D_ * N_;
    float acc = 0.0f;
    #pragma unroll
    for (int d = 0; d < D_; d++) {
        float v = X[d * N_ + n];
        acc = fmaf(v, v, acc);
    }
    g_sq[gid] = acc;
}

// ---------------------------------------------------------------------------
// 2) dist = sqrt(max(sq_i + sq_j - 2*dot, 0)). UPPER-TRIANGLE tiles (528/b),
//    cp.async double-buffered FFMA2 mainloop (proven). NEW epilogue: each
//    dist value computed ONCE (sqrtf is an expensive IEEE software sequence)
//    into the smem stage; normal AND mirror outputs are conflict-free scalar
//    copy-outs from the stage. Halves epilogue sqrt/FMUL work.
// ---------------------------------------------------------------------------
#define BUFSTRIDE 4160            // floats per buffer (A 2048 | B 2048 | pad)

__global__ __launch_bounds__(256, 2) void d2_kernel(const float* __restrict__ pc) {
    __shared__ float pool[8400];  // 2 buffers @4160; reused as 64x129 stage
    __shared__ float sqa[128];
    __shared__ float sqb[128];

    int b = blockIdx.z;
    // decode linear tile id -> (by, bx) with bx >= by  (528 tiles)
    int tl = blockIdx.x;
    int by = 0;
    #pragma unroll 1
    while (tl >= 32 - by) { tl -= 32 - by; by++; }
    int bx = by + tl;

    int i0 = by * 128;
    int j0 = bx * 128;
    const float* X = pc + (size_t)b * D_ * N_;
    int t = threadIdx.x;

    if (t < 128) sqa[t]       = g_sq[b * N_ + i0 + t];
    else         sqb[t - 128] = g_sq[b * N_ + j0 + (t - 128)];

    int r = t >> 4;    // 0..15 row group
    int c = t & 15;    // 0..15 col group
    uint32_t pbase = smem_u32(pool);

    unsigned long long acc2[8][4];   // [row][col-pair]
    #pragma unroll
    for (int ii = 0; ii < 8; ii++)
        #pragma unroll
        for (int q = 0; q < 4; q++) acc2[ii][q] = 0ull;

    auto issue = [&](int k) {
        int dc  = k * 16;
        int buf = (k & 1) * BUFSTRIDE;
        #pragma unroll
        for (int l0 = 0; l0 < 1024; l0 += 256) {   // 4 x 16B per thread
            int l   = l0 + t;
            int isB = (l >= 512);
            int ll  = l - (isB << 9);
            int d   = ll >> 5;
            int i4  = (ll & 31) << 2;
            const float* g = X + (size_t)(dc + d) * N_ + (isB ? j0 : i0) + i4;
            uint32_t s = pbase + (uint32_t)(buf + (isB ? 2048 : 0) + d * 128 + i4) * 4u;
            cpasync16(s, g);
        }
        cpcommit();
    };

    issue(0);
    issue(1);

    #pragma unroll
    for (int k = 0; k < 4; k++) {
        if (k < 3) cpwait<1>(); else cpwait<0>();
        __syncthreads();
        const float* A = pool + (k & 1) * BUFSTRIDE;
        const float* Bp = A + 2048;
        #pragma unroll
        for (int d = 0; d < 16; d++) {
            float af[8];
            *(float4*)&af[0] = *(const float4*)&A[d * 128 + r * 8];
            *(float4*)&af[4] = *(const float4*)&A[d * 128 + r * 8 + 4];
            ulonglong2 B0 = *(const ulonglong2*)&Bp[d * 128 + c * 8];
            ulonglong2 B1 = *(const ulonglong2*)&Bp[d * 128 + c * 8 + 4];
            unsigned long long bp[4] = {B0.x, B0.y, B1.x, B1.y};
            unsigned long long ap[8];
            #pragma unroll
            for (int ii = 0; ii < 8; ii++)
                asm("mov.b64 %0, {%1, %1};" : "=l"(ap[ii]) : "f"(af[ii]));
            #pragma unroll
            for (int ii = 0; ii < 8; ii++)
                #pragma unroll
                for (int q = 0; q < 4; q++)
                    fma2(acc2[ii][q], ap[ii], bp[q]);
        }
        __syncthreads();                 // all warps done reading this buffer
        if (k + 2 < 4) issue(k + 2);     // refill it for chunk k+2
    }

    // epilogue: two stage rounds, each covering output cols [64p, 64p+64).
    // Owners (c>>3 == p) compute their 64 dist values ONCE (incl. sqrt) into
    // stage[cc][i] (pitch 129 = bank spread); then all threads copy out the
    // normal rows AND (off-diag) the mirror rows, both coalesced.
    #pragma unroll
    for (int p = 0; p < 2; p++) {
        __syncthreads();            // stage (pool) free
        if ((c >> 3) == p) {
            int cl = (c & 7) * 8;   // stage row base for this thread
            #pragma unroll
            for (int ii = 0; ii < 8; ii++) {
                float si = sqa[r * 8 + ii];
                #pragma unroll
                for (int q = 0; q < 4; q++) {
                    float dx = __uint_as_float((unsigned)acc2[ii][q]);
                    float dy = __uint_as_float((unsigned)(acc2[ii][q] >> 32));
                    float s0 = si + sqb[c * 8 + 2 * q];
                    float s1 = si + sqb[c * 8 + 2 * q + 1];
                    pool[(cl + 2 * q)     * 129 + r * 8 + ii] =
                        sqrtf(fmaxf(s0 - 2.0f * dx, 0.0f));
                    pool[(cl + 2 * q + 1) * 129 + r * 8 + ii] =
                        sqrtf(fmaxf(s1 - 2.0f * dy, 0.0f));
                }
            }
        }
        __syncthreads();
        // normal copy-out: row i0+i, cols j0+64p+cc (coalesced; LDS stride
        // 129 across cc -> bank-step 1, conflict-free)
        #pragma unroll
        for (int k = 0; k < 32; k++) {
            int idx = k * 256 + t;
            int i  = idx >> 6;
            int cc = idx & 63;
            g_dist[((size_t)(b * N_ + i0 + i) << 12) + j0 + 64 * p + cc] =
                pool[cc * 129 + i];
        }
        // mirror copy-out: row j0+64p+cc, cols i0+i (coalesced; LDS reads
        // consecutive addresses, conflict-free)
        if (bx != by) {
            int jbase = j0 + p * 64;
            #pragma unroll
            for (int k = 0; k < 32; k++) {
                int idx = k * 256 + t;
                int cc = idx >> 7;
                int i  = idx & 127;
                g_dist[((size_t)(b * N_ + jbase + cc) << 12) + i0 + i] =
                    pool[cc * 129 + i];
            }
        }
    }
}

// ---------------------------------------------------------------------------
// 3) select v4: same algorithm/key-order as proven R6 version, but row values
//    are staged in SMEM instead of registers (drops val[16]+vv[4] from the
//    live set -> ~40 regs -> ~6 blocks/SM instead of ~4 for this latency-
//    bound kernel). buf shrunk to 2048 with an exact slow-path fallback
//    (block argmin over smem vals) if candidates overflow — never taken on
//    real data, preserves worst-case correctness.
// ---------------------------------------------------------------------------
__global__ __launch_bounds__(256) void select_kernel(float* __restrict__ out_idx_f) {
    __shared__ float vals[4096];                 // 16 KB
    __shared__ unsigned long long buf[2048];     // 16 KB
    __shared__ unsigned long long wred[8];
    __shared__ float wtau[8];
    __shared__ int cnt;

    int row = blockIdx.x;                      // b*4096 + i
    const float* src = g_dist + (size_t)row * N_;
    int t = threadIdx.x;
    int lane = t & 31, w = t >> 5;
    unsigned lmask_lt = (1u << lane) - 1u;

    if (t == 0) cnt = 0;

    // load phase: warp w owns cols [512w, 512w+512); stash in smem, fold min
    float mn = __int_as_float(0x7F800000);
    #pragma unroll
    for (int u = 0; u < 4; u++) {
        int f4 = 128 * w + lane + 32 * u;
        float4 v = ((const float4*)src)[f4];
        *(float4*)&vals[f4 * 4] = v;
        mn = fminf(mn, fminf(fminf(v.x, v.y), fminf(v.z, v.w)));
    }

    // bitonic sort of lane minima across the warp
    float x = mn;
    #pragma unroll
    for (int k = 2; k <= 32; k <<= 1) {
        #pragma unroll
        for (int j2 = k >> 1; j2 > 0; j2 >>= 1) {
            float other = __shfl_xor_sync(0xffffffffu, x, j2);
            bool up    = ((lane & k) == 0);
            bool small = ((lane & j2) == 0);
            x = (small == up) ? fminf(x, other) : fmaxf(x, other);
        }
    }
    float tau_w = __shfl_sync(0xffffffffu, x, K_);   // 17th smallest lane-min
    if (lane == 0) wtau[w] = tau_w;
    __syncthreads();
    float tau = wtau[0];
    #pragma unroll
    for (int q = 1; q < 8; q++) tau = fminf(tau, wtau[q]);

    // filter + warp-aggregated compaction (one atomic per warp).
    // Each lane reads back only values it wrote itself (no extra sync needed).
    unsigned msk[16];
    int tot = 0;
    #pragma unroll
    for (int e = 0; e < 16; e++) {
        int j = (128 * w + lane + 32 * (e >> 2)) * 4 + (e & 3);
        float va = vals[j];
        msk[e] = __ballot_sync(0xffffffffu, va <= tau);
        tot += __popc(msk[e]);
    }
    int wbase = 0;
    if (lane == 0) wbase = atomicAdd(&cnt, tot);
    wbase = __shfl_sync(0xffffffffu, wbase, 0);
    int off = 0;
    #pragma unroll
    for (int e = 0; e < 16; e++) {
        if (msk[e] & (1u << lane)) {
            int j = (128 * w + lane + 32 * (e >> 2)) * 4 + (e & 3);
            int pos = wbase + off + __popc(msk[e] & lmask_lt);
            if (pos < 2048)
                buf[pos] = ((unsigned long long)__float_as_uint(vals[j]) << 32)
                           | (unsigned)j;
        }
        off += __popc(msk[e]);
    }
    __syncthreads();

    int n = cnt;
    if (n <= 2048) {
        // fast path: exact top-17 on the candidate set (warp 0)
        if (w == 0) {
            for (int p = 0; p <= K_; p++) {
                unsigned long long m = 0xFFFFFFFFFFFFFFFFull;
                for (int q = lane; q < n; q += 32) m = (buf[q] < m) ? buf[q] : m;
                #pragma unroll
                for (int o2 = 16; o2; o2 >>= 1) {
                    unsigned long long o = __shfl_xor_sync(0xffffffffu, m, o2);
                    m = (o < m) ? o : m;
                }
                for (int q = lane; q < n; q += 32)
                    if (buf[q] == m) buf[q] = 0xFFFFFFFFFFFFFFFFull;
                if (lane == 0 && p > 0) {
                    int j = (int)(m & 0xFFFFFFFFu);
                    g_idx[row * K_ + (p - 1)]     = j;
                    out_idx_f[row * K_ + (p - 1)] = (float)j;
                }
            }
        }
    } else {
        // slow path (adversarial ties only): exact block argmin over smem vals
        for (int p = 0; p <= K_; p++) {
            unsigned long long best = 0xFFFFFFFFFFFFFFFFull;
            #pragma unroll
            for (int jj = 0; jj < 16; jj++) {
                int j = t + jj * 256;
                unsigned long long key =
                    ((unsigned long long)__float_as_uint(vals[j]) << 32) | (unsigned)j;
                best = (key < best) ? key : best;
            }
            #pragma unroll
            for (int o2 = 16; o2; o2 >>= 1) {
                unsigned long long o = __shfl_down_sync(0xffffffffu, best, o2);
                best = (o < best) ? o : best;
            }
            if (lane == 0) wred[w] = best;
            __syncthreads();
            if (t == 0) {
                unsigned long long bb = wred[0];
                #pragma unroll
                for (int q = 1; q < 8; q++) bb = (wred[q] < bb) ? wred[q] : bb;
                int win = (int)(bb & 0xFFFFFFFFu);
                if (p > 0) {
                    g_idx[row * K_ + (p - 1)]     = win;
                    out_idx_f[row * K_ + (p - 1)] = (float)win;
                }
                vals[win] = __int_as_float(0x7F800000);
            }
            __syncthreads();
        }
    }
}

// ---------------------------------------------------------------------------
// 4) gather v3 (measured ~37us): smem-row gather. Block = (b, channel, octant).
// ---------------------------------------------------------------------------
__global__ __launch_bounds__(256) void gather_kernel(const float* __restrict__ pc,
                                                     float* __restrict__ out) {
    __shared__ float rowv[N_];

    int blk = blockIdx.x;            // 2048 blocks: b(2) | c(6) | s(3)
    int s   = blk & 7;
    int c   = (blk >> 3) & 63;
    int b   = blk >> 9;
    int t   = threadIdx.x;
    const float* src = pc + ((size_t)b * D_ + c) * N_;

    #pragma unroll
    for (int q = 0; q < 4; q++)
        ((float4*)rowv)[t + q * 256] = ((const float4*)src)[t + q * 256];
    __syncthreads();

    int n0 = s * 512;
    const int* idxp = g_idx + ((size_t)b * N_ + n0) * K_;
    size_t obase = (size_t)b * 2 * D_ * N_ * K_ + ((size_t)c * N_ + n0) * K_;
    float* oc = out + obase;
    float* on = out + obase + (size_t)D_ * N_ * K_;

    #pragma unroll 4
    for (int it = 0; it < 32; it++) {
        int l = t + it * 256;
        int n = l >> 4;
        int j = idxp[l];
        float ce = rowv[n0 + n];
        float nb = rowv[j];
        oc[l] = ce;
        on[l] = nb - ce;
    }
}

// ---------------------------------------------------------------------------
extern "C" void kernel_launch(void* const* d_in, const int* in_sizes, int n_in,
                              void* d_out, int out_size) {
    const float* pc = (const float*)d_in[0];
    float* out = (float*)d_out;
    float* out_idx = out + (size_t)B_ * 2 * D_ * N_ * K_;

    sq_kernel<<<(B_ * N_) / 256, 256>>>(pc);
    dim3 gg(528, 1, B_);                      // upper-triangle tiles
    d2_kernel<<<gg, 256>>>(pc);
    select_kernel<<<B_ * N_, 256>>>(out_idx);
    gather_kernel<<<B_ * D_ * 8, 256>>>(pc, out);
}

// round 14
// speedup vs baseline: 1.2199x; 1.2199x over previous
#include <cuda_runtime.h>
#include <cstdint>

// EdgeFeature: B=4, D=64, N=4096, K=16
// out = [ edge_feature (4,128,4096,16) fp32 ; idx (4,65536) as fp32 ]

#define B_ 4
#define D_ 64
#define N_ 4096
#define K_ 16

// Scratch (static __device__ — no allocations allowed in kernel_launch)
__device__ float g_sq[B_ * N_];                       // 64 KB
__device__ float g_dist[(size_t)B_ * N_ * N_];        // 256 MB
__device__ int   g_idx[B_ * N_ * K_];                 // 1 MB

// packed f32x2 FMA: both lanes are independent IEEE fp32 FMAs -> bitwise
// identical to scalar fmaf chains (validated rel_err==0 across rounds).
__device__ __forceinline__ void fma2(unsigned long long& c,
                                     unsigned long long a, unsigned long long b) {
    asm("fma.rn.f32x2 %0, %1, %2, %0;" : "+l"(c) : "l"(a), "l"(b));
}

__device__ __forceinline__ uint32_t smem_u32(const void* p) {
    uint32_t a;
    asm("{ .reg .u64 t; cvta.to.shared.u64 t, %1; cvt.u32.u64 %0, t; }"
        : "=r"(a) : "l"(p));
    return a;
}
__device__ __forceinline__ void cpasync16(uint32_t saddr, const void* g) {
    asm volatile("cp.async.ca.shared.global [%0], [%1], 16;"
                 :: "r"(saddr), "l"(g) : "memory");
}
__device__ __forceinline__ void cpcommit() {
    asm volatile("cp.async.commit_group;" ::: "memory");
}
template <int N>
__device__ __forceinline__ void cpwait() {
    asm volatile("cp.async.wait_group %0;" :: "n"(N) : "memory");
}

// ---------------------------------------------------------------------------
// 1) squared norms (sequential ascending d, fmaf — matches the GEMM's dot
//    accumulation order so self-distance cancels to exactly 0.0f)
// ---------------------------------------------------------------------------
__global__ void sq_kernel(const float* __restrict__ pc) {
    int gid = blockIdx.x * blockDim.x + threadIdx.x;
    int b = gid >> 12;
    int n = gid & (N_ - 1);
    const float* X = pc + (size_t)b * D_ * N_;
    float acc = 0.0f;
    #pragma unroll
    for (int d = 0; d < D_; d++) {
        float v = X[d * N_ + n];
        acc = fmaf(v, v, acc);
    }
    g_sq[gid] = acc;
}

// ---------------------------------------------------------------------------
// 2) dist = sqrt(max(sq_i + sq_j - 2*dot, 0)). UPPER-TRIANGLE tiles (528/b),
//    cp.async double-buffered FFMA2 mainloop, compute-once staged epilogue.
//    BYTE-IDENTICAL to R13.
// ---------------------------------------------------------------------------
#define BUFSTRIDE 4160            // floats per buffer (A 2048 | B 2048 | pad)

__global__ __launch_bounds__(256, 2) void d2_kernel(const float* __restrict__ pc) {
    __shared__ float pool[8400];  // 2 buffers @4160; reused as 64x129 stage
    __shared__ float sqa[128];
    __shared__ float sqb[128];

    int b = blockIdx.z;
    int tl = blockIdx.x;
    int by = 0;
    #pragma unroll 1
    while (tl >= 32 - by) { tl -= 32 - by; by++; }
    int bx = by + tl;

    int i0 = by * 128;
    int j0 = bx * 128;
    const float* X = pc + (size_t)b * D_ * N_;
    int t = threadIdx.x;

    if (t < 128) sqa[t]       = g_sq[b * N_ + i0 + t];
    else         sqb[t - 128] = g_sq[b * N_ + j0 + (t - 128)];

    int r = t >> 4;
    int c = t & 15;
    uint32_t pbase = smem_u32(pool);

    unsigned long long acc2[8][4];
    #pragma unroll
    for (int ii = 0; ii < 8; ii++)
        #pragma unroll
        for (int q = 0; q < 4; q++) acc2[ii][q] = 0ull;

    auto issue = [&](int k) {
        int dc  = k * 16;
        int buf = (k & 1) * BUFSTRIDE;
        #pragma unroll
        for (int l0 = 0; l0 < 1024; l0 += 256) {
            int l   = l0 + t;
            int isB = (l >= 512);
            int ll  = l - (isB << 9);
            int d   = ll >> 5;
            int i4  = (ll & 31) << 2;
            const float* g = X + (size_t)(dc + d) * N_ + (isB ? j0 : i0) + i4;
            uint32_t s = pbase + (uint32_t)(buf + (isB ? 2048 : 0) + d * 128 + i4) * 4u;
            cpasync16(s, g);
        }
        cpcommit();
    };

    issue(0);
    issue(1);

    #pragma unroll
    for (int k = 0; k < 4; k++) {
        if (k < 3) cpwait<1>(); else cpwait<0>();
        __syncthreads();
        const float* A = pool + (k & 1) * BUFSTRIDE;
        const float* Bp = A + 2048;
        #pragma unroll
        for (int d = 0; d < 16; d++) {
            float af[8];
            *(float4*)&af[0] = *(const float4*)&A[d * 128 + r * 8];
            *(float4*)&af[4] = *(const float4*)&A[d * 128 + r * 8 + 4];
            ulonglong2 B0 = *(const ulonglong2*)&Bp[d * 128 + c * 8];
            ulonglong2 B1 = *(const ulonglong2*)&Bp[d * 128 + c * 8 + 4];
            unsigned long long bp[4] = {B0.x, B0.y, B1.x, B1.y};
            unsigned long long ap[8];
            #pragma unroll
            for (int ii = 0; ii < 8; ii++)
                asm("mov.b64 %0, {%1, %1};" : "=l"(ap[ii]) : "f"(af[ii]));
            #pragma unroll
            for (int ii = 0; ii < 8; ii++)
                #pragma unroll
                for (int q = 0; q < 4; q++)
                    fma2(acc2[ii][q], ap[ii], bp[q]);
        }
        __syncthreads();
        if (k + 2 < 4) issue(k + 2);
    }

    #pragma unroll
    for (int p = 0; p < 2; p++) {
        __syncthreads();
        if ((c >> 3) == p) {
            int cl = (c & 7) * 8;
            #pragma unroll
            for (int ii = 0; ii < 8; ii++) {
                float si = sqa[r * 8 + ii];
                #pragma unroll
                for (int q = 0; q < 4; q++) {
                    float dx = __uint_as_float((unsigned)acc2[ii][q]);
                    float dy = __uint_as_float((unsigned)(acc2[ii][q] >> 32));
                    float s0 = si + sqb[c * 8 + 2 * q];
                    float s1 = si + sqb[c * 8 + 2 * q + 1];
                    pool[(cl + 2 * q)     * 129 + r * 8 + ii] =
                        sqrtf(fmaxf(s0 - 2.0f * dx, 0.0f));
                    pool[(cl + 2 * q + 1) * 129 + r * 8 + ii] =
                        sqrtf(fmaxf(s1 - 2.0f * dy, 0.0f));
                }
            }
        }
        __syncthreads();
        #pragma unroll
        for (int k = 0; k < 32; k++) {
            int idx = k * 256 + t;
            int i  = idx >> 6;
            int cc = idx & 63;
            g_dist[((size_t)(b * N_ + i0 + i) << 12) + j0 + 64 * p + cc] =
                pool[cc * 129 + i];
        }
        if (bx != by) {
            int jbase = j0 + p * 64;
            #pragma unroll
            for (int k = 0; k < 32; k++) {
                int idx = k * 256 + t;
                int cc = idx >> 7;
                int i  = idx & 127;
                g_dist[((size_t)(b * N_ + jbase + cc) << 12) + i0 + i] =
                    pool[cc * 129 + i];
            }
        }
    }
}

// ---------------------------------------------------------------------------
// 3) select v5: TWO ROWS PER BLOCK (8192 blocks). Warps 0-3 own row A,
//    warps 4-7 row B (1024 cols/warp, 32 vals/lane — tau bound per warp
//    still holds). The two serial 17-pass argmin tails run CONCURRENTLY
//    (warp 0 for A, warp 4 for B). Exact u64 key (bits<<32)|j == lax.top_k.
//    Overflow fallback (adversarial only): block-wide argmin over the row
//    re-read from g_dist with +inf write-back (g_dist dead after select).
// ---------------------------------------------------------------------------
__global__ __launch_bounds__(256) void select_kernel(float* __restrict__ out_idx_f) {
    __shared__ unsigned long long buf[2][1536];   // 24 KB
    __shared__ unsigned long long wred[8];
    __shared__ float wtau[8];
    __shared__ int cnt[2];

    int R = blockIdx.x;                 // 0..8191
    int t = threadIdx.x;
    int half = t >> 7;                  // 0 = row A, 1 = row B
    int lane = t & 31, w = t >> 5;      // w: 0..7
    int hw = w & 3;                     // warp within half
    unsigned lmask_lt = (1u << lane) - 1u;
    int row = 2 * R + half;
    const float* src = g_dist + (size_t)row * N_;

    if (t < 2) cnt[t] = 0;

    // warp covers cols [hw*1024, +1024): lane reads 8 coalesced float4s
    float val[32];
    #pragma unroll
    for (int u = 0; u < 8; u++) {
        float4 v = ((const float4*)src)[hw * 256 + lane + 32 * u];
        val[4 * u + 0] = v.x; val[4 * u + 1] = v.y;
        val[4 * u + 2] = v.z; val[4 * u + 3] = v.w;
    }
    float mn = val[0];
    #pragma unroll
    for (int e = 1; e < 32; e++) mn = fminf(mn, val[e]);

    // bitonic sort of 32 lane-minima; tau_w = 17th smallest
    float x = mn;
    #pragma unroll
    for (int k = 2; k <= 32; k <<= 1) {
        #pragma unroll
        for (int j2 = k >> 1; j2 > 0; j2 >>= 1) {
            float other = __shfl_xor_sync(0xffffffffu, x, j2);
            bool up    = ((lane & k) == 0);
            bool small = ((lane & j2) == 0);
            x = (small == up) ? fminf(x, other) : fmaxf(x, other);
        }
    }
    float tau_w = __shfl_sync(0xffffffffu, x, K_);
    if (lane == 0) wtau[w] = tau_w;
    __syncthreads();
    float tau = fminf(fminf(wtau[half * 4 + 0], wtau[half * 4 + 1]),
                      fminf(wtau[half * 4 + 2], wtau[half * 4 + 3]));

    // filter + compaction in 4 groups of 8 (one atomic per warp per group)
    #pragma unroll
    for (int g = 0; g < 4; g++) {
        unsigned msk[8];
        int tot = 0;
        #pragma unroll
        for (int e = 0; e < 8; e++) {
            msk[e] = __ballot_sync(0xffffffffu, val[g * 8 + e] <= tau);
            tot += __popc(msk[e]);
        }
        int base = 0;
        if (lane == 0 && tot) base = atomicAdd(&cnt[half], tot);
        base = __shfl_sync(0xffffffffu, base, 0);
        int off = 0;
        #pragma unroll
        for (int e = 0; e < 8; e++) {
            int idx = g * 8 + e;
            if (msk[e] & (1u << lane)) {
                int j = (hw * 256 + lane + 32 * (idx >> 2)) * 4 + (idx & 3);
                int pos = base + off + __popc(msk[e] & lmask_lt);
                if (pos < 1536)
                    buf[half][pos] =
                        ((unsigned long long)__float_as_uint(val[idx]) << 32)
                        | (unsigned)j;
            }
            off += __popc(msk[e]);
        }
    }
    __syncthreads();

    // fast path: warp 0 -> row A, warp 4 -> row B (concurrent serial tails)
    if ((w == 0 || w == 4) && cnt[half] <= 1536) {
        int n = cnt[half];
        unsigned long long* bb = buf[half];
        for (int p = 0; p <= K_; p++) {
            unsigned long long m = 0xFFFFFFFFFFFFFFFFull;
            for (int q = lane; q < n; q += 32) m = (bb[q] < m) ? bb[q] : m;
            #pragma unroll
            for (int o2 = 16; o2; o2 >>= 1) {
                unsigned long long o = __shfl_xor_sync(0xffffffffu, m, o2);
                m = (o < m) ? o : m;
            }
            for (int q = lane; q < n; q += 32)
                if (bb[q] == m) bb[q] = 0xFFFFFFFFFFFFFFFFull;
            if (lane == 0 && p > 0) {
                int j = (int)(m & 0xFFFFFFFFu);
                g_idx[row * K_ + (p - 1)]     = j;
                out_idx_f[row * K_ + (p - 1)] = (float)j;
            }
        }
    }
    __syncthreads();

    // overflow fallback (adversarial ties only; never taken on real data):
    // block-wide exact 17-pass argmin over the row, +inf write-back.
    #pragma unroll 1
    for (int h = 0; h < 2; h++) {
        if (cnt[h] > 1536) {
            int rr = 2 * R + h;
            float* srow = g_dist + (size_t)rr * N_;
            for (int p = 0; p <= K_; p++) {
                unsigned long long best = 0xFFFFFFFFFFFFFFFFull;
                #pragma unroll
                for (int jj = 0; jj < 16; jj++) {
                    int j = t + jj * 256;
                    unsigned long long key =
                        ((unsigned long long)__float_as_uint(srow[j]) << 32)
                        | (unsigned)j;
                    best = (key < best) ? key : best;
                }
                #pragma unroll
                for (int o2 = 16; o2; o2 >>= 1) {
                    unsigned long long o = __shfl_down_sync(0xffffffffu, best, o2);
                    best = (o < best) ? o : best;
                }
                if (lane == 0) wred[w] = best;
                __syncthreads();
                if (t == 0) {
                    unsigned long long bb2 = wred[0];
                    #pragma unroll
                    for (int q = 1; q < 8; q++) bb2 = (wred[q] < bb2) ? wred[q] : bb2;
                    int win = (int)(bb2 & 0xFFFFFFFFu);
                    if (p > 0) {
                        g_idx[rr * K_ + (p - 1)]     = win;
                        out_idx_f[rr * K_ + (p - 1)] = (float)win;
                    }
                    srow[win] = __int_as_float(0x7F800000);
                }
                __syncthreads();
            }
        }
    }
}

// ---------------------------------------------------------------------------
// 4) gather v3 (measured ~37us): smem-row gather. Block = (b, channel, octant).
// ---------------------------------------------------------------------------
__global__ __launch_bounds__(256) void gather_kernel(const float* __restrict__ pc,
                                                     float* __restrict__ out) {
    __shared__ float rowv[N_];

    int blk = blockIdx.x;            // 2048 blocks: b(2) | c(6) | s(3)
    int s   = blk & 7;
    int c   = (blk >> 3) & 63;
    int b   = blk >> 9;
    int t   = threadIdx.x;
    const float* src = pc + ((size_t)b * D_ + c) * N_;

    #pragma unroll
    for (int q = 0; q < 4; q++)
        ((float4*)rowv)[t + q * 256] = ((const float4*)src)[t + q * 256];
    __syncthreads();

    int n0 = s * 512;
    const int* idxp = g_idx + ((size_t)b * N_ + n0) * K_;
    size_t obase = (size_t)b * 2 * D_ * N_ * K_ + ((size_t)c * N_ + n0) * K_;
    float* oc = out + obase;
    float* on = out + obase + (size_t)D_ * N_ * K_;

    #pragma unroll 4
    for (int it = 0; it < 32; it++) {
        int l = t + it * 256;
        int n = l >> 4;
        int j = idxp[l];
        float ce = rowv[n0 + n];
        float nb = rowv[j];
        oc[l] = ce;
        on[l] = nb - ce;
    }
}

// ---------------------------------------------------------------------------
extern "C" void kernel_launch(void* const* d_in, const int* in_sizes, int n_in,
                              void* d_out, int out_size) {
    const float* pc = (const float*)d_in[0];
    float* out = (float*)d_out;
    float* out_idx = out + (size_t)B_ * 2 * D_ * N_ * K_;

    sq_kernel<<<(B_ * N_) / 256, 256>>>(pc);
    dim3 gg(528, 1, B_);                      // upper-triangle tiles
    d2_kernel<<<gg, 256>>>(pc);
    select_kernel<<<B_ * N_ / 2, 256>>>(out_idx);
    gather_kernel<<<B_ * D_ * 8, 256>>>(pc, out);
}